// round 6
// baseline (speedup 1.0000x reference)
#include <cuda_runtime.h>

#define NN 50000
#define EE 640000
#define FF 128
#define GG 256
#define NC 10

// ---------------- scratch (static device globals; no allocation) ----------------
__device__ float g_x[NN * FF];
__device__ float g_h[NN * FF];
__device__ float g_stats[2 * FF];
__device__ float g_dinv[NN];
__device__ float g_selfw[NN];
__device__ int   g_rowcnt[NN];
__device__ int   g_rowptr[NN + 1];
__device__ int   g_cursor[NN];
__device__ int   g_col[EE];
__device__ float g_wgt[EE];
__device__ float g_att[NN];
__device__ int   g_goff[GG + 1];
__device__ float g_rep[GG * 3 * FF];
__device__ int   g_src[EE];
__device__ int   g_dst[EE];
__device__ int   g_batch[NN];
__device__ int   g_is32_edge;
__device__ int   g_is32_batch;

// ---------------- dtype detection (int64 metadata may actually be int32) ----------------
__global__ void k_detect(const long long* __restrict__ ei, const long long* __restrict__ batch) {
    if (threadIdx.x == 0 && blockIdx.x == 0) {
        int is32 = 0;
        for (int i = 0; i < 16; i++) {
            long long v = ei[i * 37];
            if (v < 0 || v >= (long long)NN) is32 = 1;
        }
        g_is32_edge = is32;
        long long vb = batch[NN / 2 - 1];
        g_is32_batch = (vb < 0 || vb >= (long long)GG) ? 1 : 0;
    }
}

// ---------------- init (must precede k_conv_edges: zeroes rowcnt) ----------------
__global__ void k_init() {
    int i = blockIdx.x * blockDim.x + threadIdx.x;
    if (i < NN) g_rowcnt[i] = 0;
    if (i < 2 * FF) g_stats[i] = 0.0f;
    if (i < GG * 3 * FF) g_rep[i] = 0.0f;
}

// ---------------- edge convert + degree histogram (fused) ----------------
__global__ void k_conv_edges(const void* __restrict__ ei) {
    int e = blockIdx.x * blockDim.x + threadIdx.x;
    if (e >= EE) return;
    int s, d;
    if (g_is32_edge) {
        const int* p = (const int*)ei;
        s = p[e]; d = p[EE + e];
    } else {
        const long long* p = (const long long*)ei;
        s = (int)p[e]; d = (int)p[EE + e];
    }
    s = min(max(s, 0), NN - 1);
    d = min(max(d, 0), NN - 1);
    g_src[e] = s; g_dst[e] = d;
    if (s != d) atomicAdd(&g_rowcnt[d], 1);
}

__global__ void k_conv_batch(const void* __restrict__ batch) {
    int i = blockIdx.x * blockDim.x + threadIdx.x;
    if (i >= NN) return;
    int b;
    if (g_is32_batch) b = ((const int*)batch)[i];
    else              b = (int)((const long long*)batch)[i];
    g_batch[i] = min(max(b, 0), GG - 1);
}

// ---------------- BN stats ----------------
__global__ void k_bn_stats(const float4* __restrict__ x4) {
    int f4 = threadIdx.x & 31;
    int rsub = threadIdx.x >> 5;
    float4 s = make_float4(0, 0, 0, 0);
    float4 q = make_float4(0, 0, 0, 0);
    for (int r = blockIdx.x * 8 + rsub; r < NN; r += gridDim.x * 8) {
        float4 v = x4[r * 32 + f4];
        s.x += v.x; s.y += v.y; s.z += v.z; s.w += v.w;
        q.x += v.x * v.x; q.y += v.y * v.y; q.z += v.z * v.z; q.w += v.w * v.w;
    }
    __shared__ float ss[FF], sq[FF];
    if (threadIdx.x < FF) { ss[threadIdx.x] = 0.f; sq[threadIdx.x] = 0.f; }
    __syncthreads();
    atomicAdd(&ss[f4 * 4 + 0], s.x); atomicAdd(&ss[f4 * 4 + 1], s.y);
    atomicAdd(&ss[f4 * 4 + 2], s.z); atomicAdd(&ss[f4 * 4 + 3], s.w);
    atomicAdd(&sq[f4 * 4 + 0], q.x); atomicAdd(&sq[f4 * 4 + 1], q.y);
    atomicAdd(&sq[f4 * 4 + 2], q.z); atomicAdd(&sq[f4 * 4 + 3], q.w);
    __syncthreads();
    if (threadIdx.x < FF) {
        atomicAdd(&g_stats[threadIdx.x], ss[threadIdx.x]);
        atomicAdd(&g_stats[FF + threadIdx.x], sq[threadIdx.x]);
    }
}

// ---------------- BN apply ----------------
__global__ void k_bn_apply(const float4* __restrict__ x4,
                           const float* __restrict__ gamma,
                           const float* __restrict__ beta) {
    int idx = blockIdx.x * blockDim.x + threadIdx.x;
    if (idx >= NN * 32) return;
    int f4 = idx & 31;
    float4 v = x4[idx];
    float4 o;
    float invN = 1.0f / (float)NN;
    #pragma unroll
    for (int c = 0; c < 4; c++) {
        int f = f4 * 4 + c;
        float mean = g_stats[f] * invN;
        float var = g_stats[FF + f] * invN - mean * mean;
        float istd = rsqrtf(var + 1e-5f);
        float vi = (c == 0) ? v.x : (c == 1) ? v.y : (c == 2) ? v.z : v.w;
        float r = (vi - mean) * istd * gamma[f] + beta[f];
        if (c == 0) o.x = r; else if (c == 1) o.y = r; else if (c == 2) o.z = r; else o.w = r;
    }
    ((float4*)g_x)[idx] = o;
}

__global__ void k_dinv() {
    int i = blockIdx.x * blockDim.x + threadIdx.x;
    if (i >= NN) return;
    float deg = (float)(g_rowcnt[i] + 1);   // + self loop
    float di = rsqrtf(deg);
    g_dinv[i] = di;
    g_selfw[i] = di * di;
}

// ---------------- scan: thread-serial partials + warp-shuffle block scan ----------------
__global__ void k_scan() {
    const int PER = (NN + 1023) / 1024;     // 49
    int t = threadIdx.x;
    int beg = t * PER;
    int end = min(beg + PER, NN);
    int s = 0;
    for (int j = beg; j < end; j++) s += g_rowcnt[j];
    int lane = t & 31, w = t >> 5;
    // warp inclusive scan
    int p = s;
    #pragma unroll
    for (int o = 1; o < 32; o <<= 1) {
        int u = __shfl_up_sync(0xffffffffu, p, o);
        if (lane >= o) p += u;
    }
    __shared__ int wtot[32];
    __shared__ int wexc[32];
    __shared__ int total;
    if (lane == 31) wtot[w] = p;
    __syncthreads();
    if (w == 0) {
        int q = wtot[lane];
        int qi = q;
        #pragma unroll
        for (int o = 1; o < 32; o <<= 1) {
            int u = __shfl_up_sync(0xffffffffu, qi, o);
            if (lane >= o) qi += u;
        }
        wexc[lane] = qi - q;
        if (lane == 31) total = qi;
    }
    __syncthreads();
    int run = wexc[w] + (p - s);            // exclusive prefix for this thread's range
    for (int j = beg; j < end; j++) {
        g_rowptr[j] = run;
        g_cursor[j] = run;
        run += g_rowcnt[j];
    }
    if (t == 0) g_rowptr[NN] = total;
}

// ---------------- CSR scatter with edge norms ----------------
__global__ void k_scatter() {
    int e = blockIdx.x * blockDim.x + threadIdx.x;
    if (e >= EE) return;
    int s = g_src[e], d = g_dst[e];
    if (s != d) {
        int p = atomicAdd(&g_cursor[d], 1);
        g_col[p] = s;
        g_wgt[p] = g_dinv[s] * g_dinv[d];
    }
}

// ---------------- graph segment offsets from sorted batch ----------------
__global__ void k_goff() {
    int i = blockIdx.x * blockDim.x + threadIdx.x;
    if (i >= NN) return;
    int b = g_batch[i];
    int bp = (i == 0) ? -1 : g_batch[i - 1];
    for (int g = bp + 1; g <= b; g++) g_goff[g] = i;
    if (i == NN - 1) {
        for (int g = b + 1; g <= GG; g++) g_goff[g] = NN;
    }
}

// ---------------- tf32 helpers ----------------
__device__ __forceinline__ unsigned f2tf32(float f) {
    unsigned r;
    asm("cvt.rna.tf32.f32 %0, %1;" : "=r"(r) : "f"(f));
    return r;
}
__device__ __forceinline__ void mma_tf32(float* d, unsigned a0, unsigned a1, unsigned a2, unsigned a3,
                                         unsigned b0, unsigned b1) {
    asm volatile(
        "mma.sync.aligned.m16n8k8.row.col.f32.tf32.tf32.f32 "
        "{%0,%1,%2,%3}, {%4,%5,%6,%7}, {%8,%9}, {%0,%1,%2,%3};"
        : "+f"(d[0]), "+f"(d[1]), "+f"(d[2]), "+f"(d[3])
        : "r"(a0), "r"(a1), "r"(a2), "r"(a3), "r"(b0), "r"(b1));
}

// ---------------- GEMM (tf32 tensor cores, 3xTF32 compensation) ----------------
// g_h[M,128] = g_x[M,128] @ W[128,128].  Block tile 128x128, warps 4(m) x 2(n).
#define KC 16
#define XS_STRIDE 20
__global__ void __launch_bounds__(256) k_gemm(const float* __restrict__ W) {
    __shared__ unsigned xs_hi[128 * XS_STRIDE];
    __shared__ unsigned xs_lo[128 * XS_STRIDE];
    __shared__ unsigned ws_hi[128 * XS_STRIDE];   // transposed: [n][k]
    __shared__ unsigned ws_lo[128 * XS_STRIDE];

    int tid = threadIdx.x;
    int wid = tid >> 5, lane = tid & 31;
    int g = lane >> 2, tig = lane & 3;
    int m0 = (wid & 3) * 32;          // warp m-tile base within block
    int n0 = (wid >> 2) * 64;         // warp n-tile base
    int row0 = blockIdx.x * 128;

    float acc[2][8][4];
    #pragma unroll
    for (int i = 0; i < 2; i++)
        #pragma unroll
        for (int j = 0; j < 8; j++)
            #pragma unroll
            for (int c = 0; c < 4; c++) acc[i][j][c] = 0.f;

    for (int k0 = 0; k0 < 128; k0 += KC) {
        // load x tile [128 rows x 16 k]: thread -> row=tid/2, cols (tid&1)*8..+7
        {
            int r = tid >> 1;
            int c0 = (tid & 1) * 8;
            int gr = row0 + r;
            float v[8];
            if (gr < NN) {
                float4 va = *(const float4*)&g_x[gr * 128 + k0 + c0];
                float4 vb = *(const float4*)&g_x[gr * 128 + k0 + c0 + 4];
                v[0]=va.x; v[1]=va.y; v[2]=va.z; v[3]=va.w;
                v[4]=vb.x; v[5]=vb.y; v[6]=vb.z; v[7]=vb.w;
            } else {
                #pragma unroll
                for (int q = 0; q < 8; q++) v[q] = 0.f;
            }
            #pragma unroll
            for (int q = 0; q < 8; q++) {
                unsigned hi = f2tf32(v[q]);
                float lo = v[q] - __uint_as_float(hi);
                xs_hi[r * XS_STRIDE + c0 + q] = hi;
                xs_lo[r * XS_STRIDE + c0 + q] = f2tf32(lo);
            }
        }
        // load W tile [16 k x 128 n] transposed into ws[n][k]
        {
            int kk = tid >> 4;            // 0..15
            int nb = (tid & 15) * 8;      // 0..120
            float4 va = *(const float4*)&W[(k0 + kk) * 128 + nb];
            float4 vb = *(const float4*)&W[(k0 + kk) * 128 + nb + 4];
            float v[8] = {va.x, va.y, va.z, va.w, vb.x, vb.y, vb.z, vb.w};
            #pragma unroll
            for (int q = 0; q < 8; q++) {
                unsigned hi = f2tf32(v[q]);
                float lo = v[q] - __uint_as_float(hi);
                ws_hi[(nb + q) * XS_STRIDE + kk] = hi;
                ws_lo[(nb + q) * XS_STRIDE + kk] = f2tf32(lo);
            }
        }
        __syncthreads();

        #pragma unroll
        for (int ks = 0; ks < 2; ks++) {
            int kb = ks * 8;
            unsigned ah[2][4], al[2][4];
            #pragma unroll
            for (int i = 0; i < 2; i++) {
                int r0 = (m0 + 16 * i + g) * XS_STRIDE;
                int r1 = (m0 + 16 * i + g + 8) * XS_STRIDE;
                int c0 = kb + tig, c1 = kb + tig + 4;
                ah[i][0] = xs_hi[r0 + c0]; ah[i][1] = xs_hi[r1 + c0];
                ah[i][2] = xs_hi[r0 + c1]; ah[i][3] = xs_hi[r1 + c1];
                al[i][0] = xs_lo[r0 + c0]; al[i][1] = xs_lo[r1 + c0];
                al[i][2] = xs_lo[r0 + c1]; al[i][3] = xs_lo[r1 + c1];
            }
            #pragma unroll
            for (int j = 0; j < 8; j++) {
                int nrow = (n0 + j * 8 + g) * XS_STRIDE;
                unsigned bh0 = ws_hi[nrow + kb + tig];
                unsigned bh1 = ws_hi[nrow + kb + tig + 4];
                unsigned bl0 = ws_lo[nrow + kb + tig];
                unsigned bl1 = ws_lo[nrow + kb + tig + 4];
                #pragma unroll
                for (int i = 0; i < 2; i++) {
                    mma_tf32(acc[i][j], ah[i][0], ah[i][1], ah[i][2], ah[i][3], bh0, bh1);
                    mma_tf32(acc[i][j], al[i][0], al[i][1], al[i][2], al[i][3], bh0, bh1);
                    mma_tf32(acc[i][j], ah[i][0], ah[i][1], ah[i][2], ah[i][3], bl0, bl1);
                }
            }
        }
        __syncthreads();
    }

    // epilogue: c0,c1 at (row, col..col+1); c2,c3 at (row+8, ...)
    #pragma unroll
    for (int i = 0; i < 2; i++) {
        int ra = row0 + m0 + 16 * i + g;
        int rb = ra + 8;
        #pragma unroll
        for (int j = 0; j < 8; j++) {
            int col = n0 + j * 8 + 2 * tig;
            if (ra < NN) *(float2*)&g_h[ra * 128 + col] = make_float2(acc[i][j][0], acc[i][j][1]);
            if (rb < NN) *(float2*)&g_h[rb * 128 + col] = make_float2(acc[i][j][2], acc[i][j][3]);
        }
    }
}

// ---------------- fused SpMM + bias + squash + attention dot ----------------
__global__ void k_spmm(const float* __restrict__ bias, const float* __restrict__ watt) {
    int warp = blockIdx.x * (blockDim.x >> 5) + (threadIdx.x >> 5);
    int lane = threadIdx.x & 31;
    if (warp >= NN) return;
    const float4* __restrict__ h4 = (const float4*)g_h;
    int d = warp;
    float4 hv = h4[d * 32 + lane];
    float sw = g_selfw[d];
    float4 acc = make_float4(sw * hv.x, sw * hv.y, sw * hv.z, sw * hv.w);
    int beg = g_rowptr[d], end = g_rowptr[d + 1];
    for (int base = beg; base < end; base += 32) {
        int e = base + lane;
        int c = 0; float ww = 0.f;
        if (e < end) { c = g_col[e]; ww = g_wgt[e]; }
        int cnt = end - base; if (cnt > 32) cnt = 32;
        for (int j = 0; j < cnt; j++) {
            int s = __shfl_sync(0xffffffffu, c, j);
            float wj = __shfl_sync(0xffffffffu, ww, j);
            float4 v = h4[s * 32 + lane];
            acc.x += wj * v.x; acc.y += wj * v.y;
            acc.z += wj * v.z; acc.w += wj * v.w;
        }
    }
    float4 b4 = ((const float4*)bias)[lane];
    acc.x += b4.x; acc.y += b4.y; acc.z += b4.z; acc.w += b4.w;
    float n2 = acc.x * acc.x + acc.y * acc.y + acc.z * acc.z + acc.w * acc.w;
    #pragma unroll
    for (int o = 16; o; o >>= 1) n2 += __shfl_xor_sync(0xffffffffu, n2, o);
    float scale = (n2 / (1.0f + n2)) * rsqrtf(n2 + 1e-8f);
    float4 xo = make_float4(scale * acc.x, scale * acc.y, scale * acc.z, scale * acc.w);
    ((float4*)g_x)[d * 32 + lane] = xo;
    float4 wa = ((const float4*)watt)[lane];
    float av = xo.x * wa.x + xo.y * wa.y + xo.z * wa.z + xo.w * wa.w;
    #pragma unroll
    for (int o = 16; o; o >>= 1) av += __shfl_xor_sync(0xffffffffu, av, o);
    if (lane == 0) g_att[d] = av;
}

// ---------------- per-graph readout (wsum / mean / max) ----------------
__global__ void k_readout() {
    int g = blockIdx.x, f = threadIdx.x;
    int s = g_goff[g], e = g_goff[g + 1];
    float wsum = 0.f, ssum = 0.f, mx = -3.402823e38f;
    #pragma unroll 4
    for (int i = s; i < e; i++) {
        float v = g_x[i * FF + f];
        float a = g_att[i];
        wsum += a * v;
        ssum += v;
        mx = fmaxf(mx, v);
    }
    float cnt = (float)(e - s);
    if (cnt < 1.0f) cnt = 1.0f;
    g_rep[g * 384 + f]       += wsum;
    g_rep[g * 384 + 128 + f] += ssum / cnt;
    g_rep[g * 384 + 256 + f] += (e > s) ? mx : 0.f;
}

// ---------------- MLP head + log_softmax ----------------
__global__ void k_head(const float* __restrict__ w1, const float* __restrict__ b1,
                       const float* __restrict__ w2, const float* __restrict__ b2,
                       float* __restrict__ out) {
    int g = blockIdx.x, t = threadIdx.x;
    __shared__ float srep[384];
    __shared__ float sh1[128];
    __shared__ float slog[16];
    for (int k = t; k < 384; k += 128) srep[k] = g_rep[g * 384 + k];
    __syncthreads();
    float acc = b1[t];
    #pragma unroll 8
    for (int k = 0; k < 384; k++) acc += srep[k] * w1[k * 128 + t];
    sh1[t] = fmaxf(acc, 0.f);
    __syncthreads();
    if (t < NC) {
        float a2 = b2[t];
        #pragma unroll 8
        for (int k = 0; k < 128; k++) a2 += sh1[k] * w2[k * NC + t];
        slog[t] = a2;
    }
    __syncthreads();
    if (t < NC) {
        float m = -3.402823e38f;
        for (int k = 0; k < NC; k++) m = fmaxf(m, slog[k]);
        float s = 0.f;
        for (int k = 0; k < NC; k++) s += expf(slog[k] - m);
        out[g * NC + t] = slog[t] - m - logf(s);
    }
}

// ---------------- launch ----------------
extern "C" void kernel_launch(void* const* d_in, const int* in_sizes, int n_in,
                              void* d_out, int out_size) {
    const float*     x      = (const float*)d_in[0];
    const void*      ei     = d_in[1];
    const void*      batch  = d_in[2];
    const float*     bn_g   = (const float*)d_in[3];
    const float*     bn_b   = (const float*)d_in[4];
    const float*     gcn_w  = (const float*)d_in[5];
    const float*     gcn_b  = (const float*)d_in[6];
    const float*     w_att  = (const float*)d_in[7];
    const float*     l1w    = (const float*)d_in[8];
    const float*     l1b    = (const float*)d_in[9];
    const float*     l2w    = (const float*)d_in[10];
    const float*     l2b    = (const float*)d_in[11];
    float* out = (float*)d_out;

    k_detect<<<1, 32>>>((const long long*)ei, (const long long*)batch);
    k_init<<<(GG * 3 * FF + 255) / 256, 256>>>();
    k_conv_edges<<<(EE + 255) / 256, 256>>>(ei);
    k_conv_batch<<<(NN + 255) / 256, 256>>>(batch);
    k_bn_stats<<<128, 256>>>((const float4*)x);
    k_bn_apply<<<(NN * 32 + 255) / 256, 256>>>((const float4*)x, bn_g, bn_b);
    k_dinv<<<(NN + 255) / 256, 256>>>();
    k_scan<<<1, 1024>>>();
    k_scatter<<<(EE + 255) / 256, 256>>>();
    k_goff<<<(NN + 255) / 256, 256>>>();

    for (int l = 0; l < 3; l++) {
        k_gemm<<<(NN + 127) / 128, 256>>>(gcn_w + l * FF * FF);
        k_spmm<<<(NN + 7) / 8, 256>>>(gcn_b + l * FF, w_att + l * FF);
        k_readout<<<GG, 128>>>();
    }
    k_head<<<GG, 128>>>(l1w, l1b, l2w, l2b, out);
}